// round 1
// baseline (speedup 1.0000x reference)
#include <cuda_runtime.h>
#include <math.h>

#define RW 512
#define NTHETA 180

__global__ void __launch_bounds__(256)
radon_kernel(const float* __restrict__ img, float* __restrict__ out)
{
    const int c = blockIdx.x * blockDim.x + threadIdx.x;   // 0..511
    const int t = blockIdx.y;                              // 0..179
    const int n = blockIdx.z;                              // 0..1
    const float* __restrict__ im = img + (size_t)n * RW * RW;

    float s, ct;
    sincosf((float)t * 0.017453292519943295f, &s, &ct);

    const float u  = (float)c - 255.5f;
    const float bx = fmaf(ct, u, 255.5f);   // ix = bx + s*v
    const float by = fmaf(-s, u, 255.5f);   // iy = by + ct*v

    float acc = 0.0f;

    #pragma unroll 4
    for (int r = 0; r < RW; ++r) {
        const float v  = (float)r - 255.5f;
        const float ix = fmaf(s,  v, bx);
        const float iy = fmaf(ct, v, by);

        const float xf = floorf(ix);
        const float yf = floorf(iy);
        const int   x0 = (int)xf;
        const int   y0 = (int)yf;
        const float fx = ix - xf;
        const float fy = iy - yf;

        const bool x0v = ((unsigned)x0       < (unsigned)RW);
        const bool x1v = ((unsigned)(x0 + 1) < (unsigned)RW);

        float v00 = 0.0f, v10 = 0.0f, v01 = 0.0f, v11 = 0.0f;

        if ((unsigned)y0 < (unsigned)RW) {
            const float* __restrict__ row = im + y0 * RW;
            if (x0v) v00 = __ldg(row + x0);
            if (x1v) v10 = __ldg(row + x0 + 1);
        }
        if ((unsigned)(y0 + 1) < (unsigned)RW) {
            const float* __restrict__ row = im + (y0 + 1) * RW;
            if (x0v) v01 = __ldg(row + x0);
            if (x1v) v11 = __ldg(row + x0 + 1);
        }

        const float top = fmaf(fx, v10 - v00, v00);
        const float bot = fmaf(fx, v11 - v01, v01);
        acc = fmaf(fy, bot - top, acc + top);
    }

    // out shape (N, 1, W, NTHETA): out[n][0][c][t]
    out[((size_t)n * RW + c) * NTHETA + t] = acc * (1.0f / 512.0f);
}

extern "C" void kernel_launch(void* const* d_in, const int* in_sizes, int n_in,
                              void* d_out, int out_size)
{
    const float* x = (const float*)d_in[0];
    float* out = (float*)d_out;

    dim3 block(256, 1, 1);
    dim3 grid(RW / 256, NTHETA, 2);
    radon_kernel<<<grid, block>>>(x, out);
}

// round 2
// speedup vs baseline: 1.9932x; 1.9932x over previous
#include <cuda_runtime.h>
#include <math.h>

#define RW   512
#define NT   180
#define PAD  112
#define PW   736              // padded width; 736*4B = 2944B row stride

// padded scratch: [layout 0=normal,1=transposed][n][PW*PW]
__device__ float g_pad[2][2][PW * PW];

// Build zero-padded normal + transposed copies of both images.
__global__ void __launch_bounds__(256)
prep_kernel(const float* __restrict__ img)
{
    const int idx = blockIdx.x * blockDim.x + threadIdx.x;   // 0 .. PW*PW-1
    const int n   = blockIdx.y;
    const int px  = idx % PW;
    const int py  = idx / PW;

    float val = 0.0f;
    const int x = px - PAD;
    const int y = py - PAD;
    if ((unsigned)x < (unsigned)RW && (unsigned)y < (unsigned)RW)
        val = img[((size_t)n * RW + y) * RW + x];

    g_pad[0][n][py * PW + px] = val;   // normal:      [y][x]
    g_pad[1][n][px * PW + py] = val;   // transposed:  [x][y]
}

__global__ void __launch_bounds__(256)
radon_kernel(float* __restrict__ out)
{
    const int c = blockIdx.x * blockDim.x + threadIdx.x;   // 0..511
    const int t = blockIdx.y;                              // 0..179
    const int n = blockIdx.z;                              // 0..1

    float s, ct;
    sincosf((float)t * 0.017453292519943295f, &s, &ct);

    // --- block-uniform configuration -------------------------------------
    // Pick the buffer whose contiguous ("fast") coordinate has the larger
    // lane-to-lane step, so the strided ("slow") coordinate moves least.
    const bool T = fabsf(s) > fabsf(ct);
    const float dfc = T ? -s : ct;    // d(fast)/dc
    const float dfr = T ?  ct : s;    // d(fast)/dr
    const float dsc = T ?  ct : -s;   // d(slow)/dc
    const float dsr = T ?  s  : ct;   // d(slow)/dr

    // Shear: offset each lane's r-start by k0*lane so that the lane-to-lane
    // slow-coordinate step |dsc + k0*dsr| is minimized (r order is free).
    int k0 = 0;
    {
        float b0 = fabsf(dsc);
        float b1 = fabsf(dsc + dsr);
        float b2 = fabsf(dsc - dsr);
        if (b1 < b0)            { b0 = b1; k0 = 1; }
        if (b2 < b0)            {          k0 = -1; }
    }

    const float* __restrict__ buf = &g_pad[T ? 1 : 0][n][0];

    // ---------------------------------------------------------------------
    const float u  = (float)c - 255.5f;
    const float bf = fmaf(dfc, u, 255.5f + (float)PAD);   // fast = bf + dfr*v
    const float bs = fmaf(dsc, u, 255.5f + (float)PAD);   // slow = bs + dsr*v

    int r = (k0 * (c & 31) + 512) & 511;   // sheared start, wraps mod 512

    float acc = 0.0f;

    #pragma unroll 4
    for (int j = 0; j < RW; ++j) {
        const float v  = (float)r - 255.5f;
        const float fa = fmaf(dfr, v, bf);
        const float sl = fmaf(dsr, v, bs);

        const float ff = floorf(fa);
        const float fs = floorf(sl);
        const float wf = fa - ff;
        const float ws = sl - fs;
        const int   fi = (int)ff;
        const int   si = (int)fs;

        const float* __restrict__ p = buf + si * PW + fi;
        const float v00 = __ldg(p);
        const float v01 = __ldg(p + 1);
        const float v10 = __ldg(p + PW);
        const float v11 = __ldg(p + PW + 1);

        const float top = fmaf(wf, v01 - v00, v00);
        const float bot = fmaf(wf, v11 - v10, v10);
        acc += fmaf(ws, bot - top, top);

        r = (r + 1) & 511;
    }

    // out shape (N, 1, W, NT): out[n][0][c][t]
    out[((size_t)n * RW + c) * NT + t] = acc * (1.0f / 512.0f);
}

extern "C" void kernel_launch(void* const* d_in, const int* in_sizes, int n_in,
                              void* d_out, int out_size)
{
    const float* x = (const float*)d_in[0];
    float* out = (float*)d_out;

    dim3 pblock(256, 1, 1);
    dim3 pgrid((PW * PW) / 256, 2, 1);      // PW*PW = 541696 = 2116*256
    prep_kernel<<<pgrid, pblock>>>(x);

    dim3 block(256, 1, 1);
    dim3 grid(RW / 256, NT, 2);
    radon_kernel<<<grid, block>>>(out);
}

// round 3
// speedup vs baseline: 3.4320x; 1.7219x over previous
#include <cuda_runtime.h>
#include <math.h>

#define RW   512
#define NT   180
#define PAD  112
#define PW   736              // padded width

// texel table: [layout 0=normal,1=transposed][PW*PW]
// q[y][x] = (im0[y][x], im1[y][x], im0[y][x+1], im1[y][x+1])  (layout coords)
__device__ float4 g_q[2][PW * PW];

__global__ void __launch_bounds__(256)
prep_kernel(const float* __restrict__ img)
{
    const int idx = blockIdx.x * blockDim.x + threadIdx.x;   // 0 .. PW*PW-1
    const int l   = blockIdx.y;                              // layout
    const int px  = idx % PW;
    const int py  = idx / PW;

    // image-space (row, col) for fast-position 0 and 1 in this layout
    int r0, c0, r1, c1;
    if (l == 0) { r0 = py - PAD; c0 = px - PAD; r1 = r0;          c1 = c0 + 1; }
    else        { r0 = px - PAD; c0 = py - PAD; r1 = r0 + 1;      c1 = c0;     }

    float4 v = make_float4(0.f, 0.f, 0.f, 0.f);
    if ((unsigned)r0 < (unsigned)RW && (unsigned)c0 < (unsigned)RW) {
        v.x = img[(size_t)r0 * RW + c0];
        v.y = img[(size_t)(RW * RW) + (size_t)r0 * RW + c0];
    }
    if ((unsigned)r1 < (unsigned)RW && (unsigned)c1 < (unsigned)RW) {
        v.z = img[(size_t)r1 * RW + c1];
        v.w = img[(size_t)(RW * RW) + (size_t)r1 * RW + c1];
    }
    g_q[l][py * PW + px] = v;
}

__global__ void __launch_bounds__(128)
radon_kernel(float* __restrict__ out)
{
    const int c = blockIdx.x * blockDim.x + threadIdx.x;   // 0..511
    const int t = blockIdx.y;                              // 0..179

    float s, ct;
    sincosf((float)t * 0.017453292519943295f, &s, &ct);

    // Pick layout whose contiguous ("fast") coordinate moves most with c,
    // so the strided ("slow") coordinate moves least.
    const bool T = fabsf(s) > fabsf(ct);
    const float dfc = T ? -s : ct;    // d(fast)/dc
    const float dfr = T ?  ct : s;    // d(fast)/dr
    const float dsc = T ?  ct : -s;   // d(slow)/dc
    const float dsr = T ?  s  : ct;   // d(slow)/dr

    // Shear lane start in r to minimize lane-to-lane slow-coordinate step.
    int k0 = 0;
    {
        float b0 = fabsf(dsc);
        float b1 = fabsf(dsc + dsr);
        float b2 = fabsf(dsc - dsr);
        if (b1 < b0) { b0 = b1; k0 = 1; }
        if (b2 < b0) {          k0 = -1; }
    }

    const float4* __restrict__ buf = &g_q[T ? 1 : 0][0];

    const float u  = (float)c - 255.5f;
    const float bf = fmaf(dfc, u, 255.5f + (float)PAD);   // fast = bf + dfr*v
    const float bs = fmaf(dsc, u, 255.5f + (float)PAD);   // slow = bs + dsr*v

    int r = (k0 * (c & 31) + 512) & 511;   // sheared start (r order is free)

    float acc0 = 0.0f, acc1 = 0.0f;

    #pragma unroll 4
    for (int j = 0; j < RW; ++j) {
        const float v  = (float)r - 255.5f;
        const float fa = fmaf(dfr, v, bf);
        const float sl = fmaf(dsr, v, bs);

        const float ff = floorf(fa);
        const float fs = floorf(sl);
        const float wf = fa - ff;
        const float ws = sl - fs;
        const int   fi = (int)ff;
        const int   si = (int)fs;

        const float4* __restrict__ p = buf + si * PW + fi;
        const float4 A = __ldg(p);          // v00_0, v00_1, v01_0, v01_1
        const float4 B = __ldg(p + PW);     // v10_0, v10_1, v11_0, v11_1

        const float top0 = fmaf(wf, A.z - A.x, A.x);
        const float top1 = fmaf(wf, A.w - A.y, A.y);
        const float bot0 = fmaf(wf, B.z - B.x, B.x);
        const float bot1 = fmaf(wf, B.w - B.y, B.y);
        acc0 += fmaf(ws, bot0 - top0, top0);
        acc1 += fmaf(ws, bot1 - top1, top1);

        r = (r + 1) & 511;
    }

    // out shape (N, 1, W, NT): out[n][0][c][t]
    out[(size_t)c * NT + t]                     = acc0 * (1.0f / 512.0f);
    out[(size_t)(RW + c) * NT + t]              = acc1 * (1.0f / 512.0f);
}

extern "C" void kernel_launch(void* const* d_in, const int* in_sizes, int n_in,
                              void* d_out, int out_size)
{
    const float* x = (const float*)d_in[0];
    float* out = (float*)d_out;

    dim3 pblock(256, 1, 1);
    dim3 pgrid((PW * PW) / 256, 2, 1);      // PW*PW = 541696 = 2116*256
    prep_kernel<<<pgrid, pblock>>>(x);

    dim3 block(128, 1, 1);
    dim3 grid(RW / 128, NT, 1);
    radon_kernel<<<grid, block>>>(out);
}